// round 14
// baseline (speedup 1.0000x reference)
#include <cuda_runtime.h>
#include <cuda_bf16.h>
#include <cstdint>
#include <cstddef>

#define Nn 1024
#define BATCH 4096
#define NL 8
#define NB 128

// ---------------- device scratch (no allocations allowed) ----------------
__device__ float g_A[Nn * Nn];
__device__ float g_Linv[Nn * Nn];  // zero-init; strict upper (outside diag blocks) never written
__device__ float g_tmp[Nn * Nn];
__device__ float g_W[Nn * Nn];
__device__ float g_T[Nn * Nn];
__device__ float g_gamma[Nn * Nn];
__device__ float g_S[Nn * Nn];
__device__ float g_aw[Nn * Nn];
__device__ float g_cur[BATCH * Nn];
__device__ float g_cur2[BATCH * Nn];

// ================= bf16x3-split GEMM on tensor cores (mma.sync), pipelined ============
#define SMS 72
#define STG_ELEMS 27648
static const int MMA_SMEM = 2 * STG_ELEMS * (int)sizeof(__nv_bfloat16);  // 110592

__device__ __forceinline__ void mma16816(float* c, uint32_t a0, uint32_t a1, uint32_t a2,
                                         uint32_t a3, uint32_t b0, uint32_t b1) {
    asm volatile(
        "mma.sync.aligned.m16n8k16.row.col.f32.bf16.bf16.f32 "
        "{%0,%1,%2,%3},{%4,%5,%6,%7},{%8,%9},{%0,%1,%2,%3};\n"
        : "+f"(c[0]), "+f"(c[1]), "+f"(c[2]), "+f"(c[3])
        : "r"(a0), "r"(a1), "r"(a2), "r"(a3), "r"(b0), "r"(b1));
}

__device__ __forceinline__ void split2(float v, __nv_bfloat16& h, __nv_bfloat16& m) {
    h = __float2bfloat16(v);
    m = __float2bfloat16(v - __bfloat162float(h));
}

template <int TRA, int TRB>
__global__ __launch_bounds__(256, 2) void gemm_mma(
    const float* __restrict__ A, int lda, long long strA, const float* __restrict__ B,
    int ldb, long long strB, int K, float* __restrict__ C, int ldc, long long strC,
    const float* __restrict__ bias, float alpha, float beta, float diagAdd, int flags) {
    const int bi = blockIdx.y, bj = blockIdx.x;
    if ((flags & 2) && 2 * bj > bi) return;
    A += (long long)blockIdx.z * strA;
    B += (long long)blockIdx.z * strB;
    C += (long long)blockIdx.z * strC;
    extern __shared__ __nv_bfloat16 sm[];
    const int tid = threadIdx.x, wid = tid >> 5, lane = tid & 31;
    const int wy = wid >> 2, wx = wid & 3;
    const int g = lane >> 2, tg = lane & 3;
    const int m0 = bi * 64, n0 = bj * 128;

    float aReg[16], bReg[32];
    float acc[2][4][4];
#pragma unroll
    for (int i = 0; i < 2; ++i)
#pragma unroll
        for (int j = 0; j < 4; ++j)
#pragma unroll
            for (int q = 0; q < 4; ++q) acc[i][j][q] = 0.0f;

    const int T = K >> 6;

    auto loadT = [&](int t) {
        const int k0 = t << 6;
        if (!TRA) {
#pragma unroll
            for (int it = 0; it < 4; ++it) {
                int idx = tid + it * 256;
                int r = idx >> 4, q = (idx & 15) << 2;
                *(float4*)(aReg + it * 4) =
                    *(const float4*)(A + (size_t)(m0 + r) * lda + k0 + q);
            }
        } else {
            const int r = tid & 63, cb = (tid >> 6) << 4;
            const float* src = A + (size_t)(k0 + cb) * lda + m0 + r;
#pragma unroll
            for (int j = 0; j < 16; ++j) aReg[j] = src[(size_t)j * lda];
        }
        if (!TRB) {
#pragma unroll
            for (int it = 0; it < 8; ++it) {
                int idx = tid + it * 256;
                int r = idx >> 4, q = (idx & 15) << 2;
                *(float4*)(bReg + it * 4) =
                    *(const float4*)(B + (size_t)(n0 + r) * ldb + k0 + q);
            }
        } else {
            const int r = tid & 127, cb = (tid >> 7) << 5;
            const float* src = B + (size_t)(k0 + cb) * ldb + n0 + r;
#pragma unroll
            for (int j = 0; j < 32; ++j) bReg[j] = src[(size_t)j * ldb];
        }
    };

    auto storeT = [&](int st) {
        __nv_bfloat16* Ah = sm + st * STG_ELEMS;
        __nv_bfloat16* Am = Ah + 4608;
        __nv_bfloat16* Bh = Ah + 9216;
        __nv_bfloat16* Bm = Ah + 18432;
        if (!TRA) {
#pragma unroll
            for (int it = 0; it < 4; ++it) {
                int idx = tid + it * 256;
                int r = idx >> 4, q = (idx & 15) << 2;
                uint32_t hp[2], mp[2];
#pragma unroll
                for (int w = 0; w < 2; ++w) {
                    __nv_bfloat16 h0, h1, mq0, mq1;
                    split2(aReg[it * 4 + 2 * w], h0, mq0);
                    split2(aReg[it * 4 + 2 * w + 1], h1, mq1);
                    hp[w] = (uint32_t)__bfloat16_as_ushort(h0) |
                            ((uint32_t)__bfloat16_as_ushort(h1) << 16);
                    mp[w] = (uint32_t)__bfloat16_as_ushort(mq0) |
                            ((uint32_t)__bfloat16_as_ushort(mq1) << 16);
                }
                *(uint2*)(Ah + r * SMS + q) = make_uint2(hp[0], hp[1]);
                *(uint2*)(Am + r * SMS + q) = make_uint2(mp[0], mp[1]);
            }
        } else {
            const int r = tid & 63, cb = (tid >> 6) << 4;
#pragma unroll
            for (int j = 0; j < 16; ++j) {
                __nv_bfloat16 h, m;
                split2(aReg[j], h, m);
                Ah[r * SMS + cb + j] = h;
                Am[r * SMS + cb + j] = m;
            }
        }
        if (!TRB) {
#pragma unroll
            for (int it = 0; it < 8; ++it) {
                int idx = tid + it * 256;
                int r = idx >> 4, q = (idx & 15) << 2;
                uint32_t hp[2], mp[2];
#pragma unroll
                for (int w = 0; w < 2; ++w) {
                    __nv_bfloat16 h0, h1, mq0, mq1;
                    split2(bReg[it * 4 + 2 * w], h0, mq0);
                    split2(bReg[it * 4 + 2 * w + 1], h1, mq1);
                    hp[w] = (uint32_t)__bfloat16_as_ushort(h0) |
                            ((uint32_t)__bfloat16_as_ushort(h1) << 16);
                    mp[w] = (uint32_t)__bfloat16_as_ushort(mq0) |
                            ((uint32_t)__bfloat16_as_ushort(mq1) << 16);
                }
                *(uint2*)(Bh + r * SMS + q) = make_uint2(hp[0], hp[1]);
                *(uint2*)(Bm + r * SMS + q) = make_uint2(mp[0], mp[1]);
            }
        } else {
            const int r = tid & 127, cb = (tid >> 7) << 5;
#pragma unroll
            for (int j = 0; j < 32; ++j) {
                __nv_bfloat16 h, m;
                split2(bReg[j], h, m);
                Bh[r * SMS + cb + j] = h;
                Bm[r * SMS + cb + j] = m;
            }
        }
    };

    auto compute = [&](int st) {
        const __nv_bfloat16* base = sm + st * STG_ELEMS;
#pragma unroll
        for (int p = 0; p < 3; ++p) {
            const __nv_bfloat16* As = base + (p == 2 ? 4608 : 0);
            const __nv_bfloat16* Bs = base + (p == 1 ? 18432 : 9216);
#pragma unroll
            for (int kk = 0; kk < 4; ++kk) {
                uint32_t af[2][4], bf[4][2];
#pragma unroll
                for (int mt = 0; mt < 2; ++mt) {
                    const __nv_bfloat16* p0 =
                        As + (wy * 32 + mt * 16 + g) * SMS + kk * 16 + 2 * tg;
                    const __nv_bfloat16* p1 = p0 + 8 * SMS;
                    af[mt][0] = *(const uint32_t*)p0;
                    af[mt][1] = *(const uint32_t*)p1;
                    af[mt][2] = *(const uint32_t*)(p0 + 8);
                    af[mt][3] = *(const uint32_t*)(p1 + 8);
                }
#pragma unroll
                for (int nt = 0; nt < 4; ++nt) {
                    const __nv_bfloat16* p0 =
                        Bs + (wx * 32 + nt * 8 + g) * SMS + kk * 16 + 2 * tg;
                    bf[nt][0] = *(const uint32_t*)p0;
                    bf[nt][1] = *(const uint32_t*)(p0 + 8);
                }
#pragma unroll
                for (int mt = 0; mt < 2; ++mt)
#pragma unroll
                    for (int nt = 0; nt < 4; ++nt)
                        mma16816(acc[mt][nt], af[mt][0], af[mt][1], af[mt][2], af[mt][3],
                                 bf[nt][0], bf[nt][1]);
            }
        }
    };

    loadT(0);
    storeT(0);
    __syncthreads();
    for (int t = 0; t < T; ++t) {
        if (t + 1 < T) loadT(t + 1);
        compute(t & 1);
        if (t + 1 < T) storeT((t + 1) & 1);
        __syncthreads();
    }

#pragma unroll
    for (int mt = 0; mt < 2; ++mt) {
#pragma unroll
        for (int nt = 0; nt < 4; ++nt) {
#pragma unroll
            for (int half = 0; half < 2; ++half) {
                int r = m0 + wy * 32 + mt * 16 + g + half * 8;
                int c = n0 + wx * 32 + nt * 8 + 2 * tg;
                float v0 = alpha * acc[mt][nt][half * 2 + 0];
                float v1 = alpha * acc[mt][nt][half * 2 + 1];
                if (bias) { v0 += bias[c]; v1 += bias[c + 1]; }
                if (beta != 0.0f) {
                    v0 += beta * C[(size_t)r * ldc + c];
                    v1 += beta * C[(size_t)r * ldc + c + 1];
                }
                if (diagAdd != 0.0f) {
                    if (r == c) v0 += diagAdd;
                    if (r == c + 1) v1 += diagAdd;
                }
                if (flags & 1) { v0 = fmaxf(v0, 0.0f); v1 = fmaxf(v1, 0.0f); }
                *(float2*)(C + (size_t)r * ldc + c) = make_float2(v0, v1);
            }
        }
    }
}

// ================= potrf v4 (128x128 diag block) + diag-block inverse =================
// Warp-local 32x32 diag factor (smem + __syncwarp, no block barriers in the column
// loop), per-row forward-substitution sub-panel trsm, balanced rank-32 trailing syrk,
// warp-local inversions + bisection combines (R8-proven). Dinv -> Linv diag (ld=ldd).
// ~12 block barriers per call (was ~390).
extern __shared__ float s_potrf[];
__global__ __launch_bounds__(256) void potrf_diag_kernel(float* A, int lda, int k,
                                                         float* Dv, int ldd) {
    float* sL = s_potrf;              // [128*129]
    float* sX = s_potrf + 128 * 129;  // [128*129]
    float* sc = sX + 128 * 129;       // [64*64] scratch
    const int tid = threadIdx.x, warp = tid >> 5, lane = tid & 31;
    float* Ab = A + (size_t)k * NB * lda + (size_t)k * NB;

    for (int idx = tid; idx < NB * NB; idx += 256) {
        int r = idx >> 7, c = idx & 127;
        sL[r * 129 + c] = Ab[(size_t)r * lda + c];
    }
    for (int idx = tid; idx < 128 * 129; idx += 256) sX[idx] = 0.0f;
    __syncthreads();

    for (int p = 0; p < 4; ++p) {
        const int pj = p * 32, pe = pj + 32;
        // ---- warp 0: factor the 32x32 diag block (warp-synchronous, smem) ----
        if (warp == 0) {
            float* D = sL + pj * 129 + pj;  // element (r,c) at D[r*129+c]
            for (int j = 0; j < 32; ++j) {
                if (lane == j) D[j * 129 + j] = sqrtf(D[j * 129 + j]);
                __syncwarp();
                float invd = 1.0f / D[j * 129 + j];
                if (lane > j) D[lane * 129 + j] *= invd;
                __syncwarp();
                if (lane > j) {
                    float lrj = D[lane * 129 + j];
                    for (int c = j + 1; c <= lane; ++c)
                        D[lane * 129 + c] -= lrj * D[c * 129 + j];
                }
                __syncwarp();
            }
        }
        __syncthreads();
        if (pe < 128) {
            // ---- trsm rows pe..127: row := row * L11^{-T} (forward substitution) ----
            const int i = pe + tid;
            if (i < 128) {
                float a[32];
#pragma unroll
                for (int j = 0; j < 32; ++j) a[j] = sL[i * 129 + pj + j];
#pragma unroll
                for (int j = 0; j < 32; ++j) {
                    float s = a[j];
                    for (int kk = 0; kk < j; ++kk)
                        s -= a[kk] * sL[(pj + j) * 129 + pj + kk];
                    a[j] = s / sL[(pj + j) * 129 + pj + j];
                }
#pragma unroll
                for (int j = 0; j < 32; ++j) sL[i * 129 + pj + j] = a[j];
            }
            __syncthreads();
            // ---- rank-32 trailing syrk (lower only), balanced ----
            const int rr = tid & 127, half = tid >> 7;
            if (rr < 128 - pe) {
                const int i2 = pe + rr;
                float a[32];
#pragma unroll
                for (int kk = 0; kk < 32; ++kk) a[kk] = sL[i2 * 129 + pj + kk];
                for (int c = pe + half; c <= i2; c += 2) {
                    float s = 0.0f;
#pragma unroll
                    for (int kk = 0; kk < 32; ++kk) s += a[kk] * sL[c * 129 + pj + kk];
                    sL[i2 * 129 + c] -= s;
                }
            }
            __syncthreads();
        }
    }

    // ---- Dinv = inv(L): 4 warp-local 32x32 inversions ----
    if (warp < 4) {
        const int b = warp * 32, c = lane;
        float x[32];
#pragma unroll
        for (int r = 0; r < 32; ++r) x[r] = 0.0f;
#pragma unroll
        for (int r = 0; r < 32; ++r) {
            if (r >= c) {
                float s = (r == c) ? 1.0f : 0.0f;
#pragma unroll
                for (int kk = 0; kk < 32; ++kk)
                    if (kk >= c && kk < r) s -= sL[(b + r) * 129 + b + kk] * x[kk];
                x[r] = s / sL[(b + r) * 129 + b + r];
            }
        }
#pragma unroll
        for (int r = 0; r < 32; ++r) sX[(b + r) * 129 + b + c] = x[r];
    }
    __syncthreads();
    // ---- combine 32 -> 64 (two pairs): X21 = -X22 * L21 * X11 ----
    {
        const int p2 = tid >> 7, t = tid & 127;
        const int b = p2 * 64;
        float* tmp = sc + p2 * 1024;
#pragma unroll
        for (int q = 0; q < 8; ++q) {
            int idx = t + q * 128;
            int r = idx >> 5, c = idx & 31;
            float s = 0.0f;
#pragma unroll
            for (int kk = 0; kk < 32; ++kk)
                s += sL[(b + 32 + r) * 129 + b + kk] * sX[(b + kk) * 129 + b + c];
            tmp[r * 32 + c] = s;
        }
        __syncthreads();
#pragma unroll
        for (int q = 0; q < 8; ++q) {
            int idx = t + q * 128;
            int r = idx >> 5, c = idx & 31;
            float s = 0.0f;
#pragma unroll
            for (int kk = 0; kk < 32; ++kk)
                s += sX[(b + 32 + r) * 129 + b + 32 + kk] * tmp[kk * 32 + c];
            sX[(b + 32 + r) * 129 + b + c] = -s;
        }
    }
    __syncthreads();
    // ---- combine 64 -> 128: X21 = -X22 * L21 * X11 ----
    {
#pragma unroll
        for (int q = 0; q < 16; ++q) {
            int idx = tid + q * 256;
            int r = idx >> 6, c = idx & 63;
            float s = 0.0f;
            for (int kk = 0; kk < 64; ++kk)
                s += sL[(64 + r) * 129 + kk] * sX[kk * 129 + c];
            sc[r * 64 + c] = s;
        }
        __syncthreads();
#pragma unroll
        for (int q = 0; q < 16; ++q) {
            int idx = tid + q * 256;
            int r = idx >> 6, c = idx & 63;
            float s = 0.0f;
            for (int kk = 0; kk < 64; ++kk)
                s += sX[(64 + r) * 129 + 64 + kk] * sc[kk * 64 + c];
            sX[(64 + r) * 129 + c] = -s;
        }
    }
    __syncthreads();
    // ---- write out: L (lower, zero upper) into A, Dinv into Linv diag block ----
    for (int idx = tid; idx < NB * NB; idx += 256) {
        int r = idx >> 7, c = idx & 127;
        Ab[(size_t)r * lda + c] = (c <= r) ? sL[r * 129 + c] : 0.0f;
        Dv[(size_t)r * ldd + c] = sX[r * 129 + c];
    }
}

// ================= small utility kernels =================
__global__ void transpose_kernel(const float* __restrict__ src, float* __restrict__ dst) {
    __shared__ float t[32][33];
    int bx = blockIdx.x * 32, by = blockIdx.y * 32;
    t[threadIdx.y][threadIdx.x] = src[(size_t)(by + threadIdx.y) * Nn + bx + threadIdx.x];
    __syncthreads();
    dst[(size_t)(bx + threadIdx.y) * Nn + by + threadIdx.x] = t[threadIdx.x][threadIdx.y];
}

// ================= host orchestration =================
template <int TRA, int TRB>
static void gm(const float* A, int lda, long long sA, const float* B, int ldb, long long sB,
               int K, float* C, int ldc, long long sC, int M, int N, const float* bias,
               float alpha, float beta, float dAdd, int flags, int batch) {
    gemm_mma<TRA, TRB><<<dim3(N / 128, M / 64, batch), 256, MMA_SMEM>>>(
        A, lda, sA, B, ldb, sB, K, C, ldc, sC, bias, alpha, beta, dAdd, flags);
}

static const int POTRF_SMEM = (2 * 128 * 129 + 64 * 64) * (int)sizeof(float);  // 148480

// Cholesky of A (in place, lower) + diag-block inverses written into Linv diagonal.
static void chol_inplace(float* A, float* Linv) {
    for (int k = 0; k < Nn / NB; ++k) {
        float* Dv = Linv + (size_t)k * NB * (Nn + 1);
        potrf_diag_kernel<<<1, 256, POTRF_SMEM>>>(A, Nn, k, Dv, Nn);
        int rem = Nn - (k + 1) * NB;
        if (rem > 0) {
            float* panel = A + (size_t)(k + 1) * NB * Nn + (size_t)k * NB;
            // panel := panel * Dinv^T (in place; blocks only read their own rows)
            gm<0, 0>(panel, Nn, 0, Dv, Nn, 0, NB, panel, Nn, 0, rem, NB, nullptr, 1.0f,
                     0.0f, 0.0f, 0, 1);
            // trailing syrk (lower tiles only): At -= panel * panel^T
            float* At = A + (size_t)(k + 1) * NB * Nn + (size_t)(k + 1) * NB;
            gm<0, 0>(panel, Nn, 0, panel, Nn, 0, NB, At, Nn, 0, rem, rem, nullptr, -1.0f,
                     1.0f, 0.0f, 2, 1);
        }
    }
}

// Block-bisection inverse: diag blocks already in Linv (from potrf); upper stays zero.
static void build_linv(const float* A, float* Linv, float* tmp) {
    for (int s = 128; s <= 512; s <<= 1) {
        int P = Nn / (2 * s);
        long long str = 2LL * s * (Nn + 1);
        gm<0, 1>(A + (long long)s * Nn, Nn, str, Linv, Nn, str, s, tmp, s, (long long)s * s,
                 s, s, nullptr, 1.0f, 0.0f, 0.0f, 0, P);
        gm<0, 1>(Linv + (long long)s * (Nn + 1), Nn, str, tmp, s, (long long)s * s, s,
                 Linv + (long long)s * Nn, Nn, str, s, s, nullptr, -1.0f, 0.0f, 0.0f, 0, P);
    }
}

extern "C" void kernel_launch(void* const* d_in, const int* in_sizes, int n_in, void* d_out,
                              int out_size) {
    const float* x = (const float*)d_in[0];
    const float* Va = (const float*)d_in[1];
    const float* ba = (const float*)d_in[2];
    const float* Vin = (const float*)d_in[3];
    const float* bin = (const float*)d_in[4];
    const float* Vb = (const float*)d_in[5];
    float* out = (float*)d_out;

    float *dA, *dLinv, *dTmp, *dW, *dT, *dGamma, *dS, *dAw, *dCur, *dCur2;
    cudaGetSymbolAddress((void**)&dA, g_A);
    cudaGetSymbolAddress((void**)&dLinv, g_Linv);
    cudaGetSymbolAddress((void**)&dTmp, g_tmp);
    cudaGetSymbolAddress((void**)&dW, g_W);
    cudaGetSymbolAddress((void**)&dT, g_T);
    cudaGetSymbolAddress((void**)&dGamma, g_gamma);
    cudaGetSymbolAddress((void**)&dS, g_S);
    cudaGetSymbolAddress((void**)&dAw, g_aw);
    cudaGetSymbolAddress((void**)&dCur, g_cur);
    cudaGetSymbolAddress((void**)&dCur2, g_cur2);
    cudaFuncSetAttribute(potrf_diag_kernel, cudaFuncAttributeMaxDynamicSharedMemorySize,
                         POTRF_SMEM);
    cudaFuncSetAttribute(gemm_mma<0, 0>, cudaFuncAttributeMaxDynamicSharedMemorySize,
                         MMA_SMEM);
    cudaFuncSetAttribute(gemm_mma<0, 1>, cudaFuncAttributeMaxDynamicSharedMemorySize,
                         MMA_SMEM);
    cudaFuncSetAttribute(gemm_mma<1, 1>, cudaFuncAttributeMaxDynamicSharedMemorySize,
                         MMA_SMEM);

    // ---- Layer A: M = I + Va^T Va ; factor ; Linv ; a_weight = Va Linv^T ----
    gm<1, 1>(Va, Nn, 0, Va, Nn, 0, Nn, dA, Nn, 0, Nn, Nn, nullptr, 1.0f, 0.0f, 1.0f, 2, 1);
    chol_inplace(dA, dLinv);
    build_linv(dA, dLinv, dTmp);
    gm<0, 0>(Va, Nn, 0, dLinv, Nn, 0, Nn, dAw, Nn, 0, Nn, Nn, nullptr, 1.0f, 0.0f, 0.0f, 0, 1);

    // first = x @ a_weight^T + ba -> out
    gm<0, 0>(x, Nn, 0, dAw, Nn, 0, Nn, out, Nn, 0, BATCH, Nn, ba, 1.0f, 0.0f, 0.0f, 0, 1);
    cudaMemcpyAsync(dCur, x, (size_t)BATCH * Nn * sizeof(float), cudaMemcpyDeviceToDevice);

    float* cur = dCur;
    float* cur2 = dCur2;
    for (int i = 0; i < NL; ++i) {
        // T = gamma @ Linv^T  (layer 0: gamma = I -> T = Linv^T)
        if (i == 0)
            transpose_kernel<<<dim3(32, 32), dim3(32, 32)>>>(dLinv, dT);
        else
            gm<0, 0>(dGamma, Nn, 0, dLinv, Nn, 0, Nn, dT, Nn, 0, Nn, Nn, nullptr, 1.0f,
                     0.0f, 0.0f, 0, 1);
        // W = V_i @ Linv^T
        gm<0, 0>(Vin + (size_t)i * Nn * Nn, Nn, 0, dLinv, Nn, 0, Nn, dW, Nn, 0, Nn, Nn,
                 nullptr, 1.0f, 0.0f, 0.0f, 0, 1);
        // cur = relu(cur @ W^T + b_i)
        gm<0, 0>(cur, Nn, 0, dW, Nn, 0, Nn, cur2, Nn, 0, BATCH, Nn, bin + (size_t)i * Nn,
                 1.0f, 0.0f, 0.0f, 1, 1);
        { float* t = cur; cur = cur2; cur2 = t; }
        // S += T T^T (symmetric accumulator; replaces per-layer sigma choleskys)
        gm<0, 0>(dT, Nn, 0, dT, Nn, 0, Nn, dS, Nn, 0, Nn, Nn, nullptr, 1.0f,
                 (i == 0) ? 0.0f : 1.0f, 0.0f, 0, 1);
        // gamma = T @ W^T
        gm<0, 0>(dT, Nn, 0, dW, Nn, 0, Nn, dGamma, Nn, 0, Nn, Nn, nullptr, 1.0f, 0.0f,
                 0.0f, 0, 1);
        // M = I + 0.5 W W^T ; factor ; Linv
        gm<0, 0>(dW, Nn, 0, dW, Nn, 0, Nn, dA, Nn, 0, Nn, Nn, nullptr, 0.5f, 0.0f, 1.0f, 2, 1);
        chol_inplace(dA, dLinv);
        build_linv(dA, dLinv, dTmp);
    }

    // ---- Final layer B ----
    gm<0, 0>(Vb, Nn, 0, dLinv, Nn, 0, Nn, dGamma, Nn, 0, Nn, Nn, nullptr, 1.0f, 0.0f, 0.0f, 0, 1);
    gm<0, 0>(dAw, Nn, 0, dS, Nn, 0, Nn, dT, Nn, 0, Nn, Nn, nullptr, 1.0f, 0.0f, 0.0f, 0, 1);
    gm<0, 0>(dT, Nn, 0, dAw, Nn, 0, Nn, dA, Nn, 0, Nn, Nn, nullptr, 1.0f, 0.0f, 1.0f, 2, 1);
    chol_inplace(dA, dLinv);
    build_linv(dA, dLinv, dTmp);
    gm<1, 1>(dLinv, Nn, 0, dGamma, Nn, 0, Nn, dW, Nn, 0, Nn, Nn, nullptr, 1.0f, 0.0f, 0.0f, 0, 1);
    gm<0, 0>(cur, Nn, 0, dW, Nn, 0, Nn, out, Nn, 0, BATCH, Nn, nullptr, 1.0f, 1.0f, 0.0f, 0, 1);
}

// round 16
// speedup vs baseline: 1.1321x; 1.1321x over previous
#include <cuda_runtime.h>
#include <cuda_bf16.h>
#include <cstdint>
#include <cstddef>

#define Nn 1024
#define BATCH 4096
#define NL 8
#define NB 128

// ---------------- device scratch (no allocations allowed) ----------------
__device__ float g_A[Nn * Nn];
__device__ float g_Linv[Nn * Nn];
__device__ float g_tmp[Nn * Nn];
__device__ float g_W[Nn * Nn];
__device__ float g_T[Nn * Nn];
__device__ float g_gamma[Nn * Nn];
__device__ float g_S[Nn * Nn];
__device__ float g_aw[Nn * Nn];
__device__ float g_cur[BATCH * Nn];
__device__ float g_cur2[BATCH * Nn];

// ================= bf16x3-split GEMM on tensor cores (mma.sync), pipelined ============
#define SMS 72
#define STG_ELEMS 27648
static const int MMA_SMEM = 2 * STG_ELEMS * (int)sizeof(__nv_bfloat16);  // 110592

__device__ __forceinline__ void mma16816(float* c, uint32_t a0, uint32_t a1, uint32_t a2,
                                         uint32_t a3, uint32_t b0, uint32_t b1) {
    asm volatile(
        "mma.sync.aligned.m16n8k16.row.col.f32.bf16.bf16.f32 "
        "{%0,%1,%2,%3},{%4,%5,%6,%7},{%8,%9},{%0,%1,%2,%3};\n"
        : "+f"(c[0]), "+f"(c[1]), "+f"(c[2]), "+f"(c[3])
        : "r"(a0), "r"(a1), "r"(a2), "r"(a3), "r"(b0), "r"(b1));
}

__device__ __forceinline__ void split2(float v, __nv_bfloat16& h, __nv_bfloat16& m) {
    h = __float2bfloat16(v);
    m = __float2bfloat16(v - __bfloat162float(h));
}

template <int TRA, int TRB>
__global__ __launch_bounds__(256, 2) void gemm_mma(
    const float* __restrict__ A, int lda, long long strA, const float* __restrict__ B,
    int ldb, long long strB, int K, float* __restrict__ C, int ldc, long long strC,
    const float* __restrict__ bias, float alpha, float beta, float diagAdd, int flags) {
    const int bi = blockIdx.y, bj = blockIdx.x;
    if ((flags & 2) && 2 * bj > bi) return;
    A += (long long)blockIdx.z * strA;
    B += (long long)blockIdx.z * strB;
    C += (long long)blockIdx.z * strC;
    extern __shared__ __nv_bfloat16 sm[];
    const int tid = threadIdx.x, wid = tid >> 5, lane = tid & 31;
    const int wy = wid >> 2, wx = wid & 3;
    const int g = lane >> 2, tg = lane & 3;
    const int m0 = bi * 64, n0 = bj * 128;

    float aReg[16], bReg[32];
    float acc[2][4][4];
#pragma unroll
    for (int i = 0; i < 2; ++i)
#pragma unroll
        for (int j = 0; j < 4; ++j)
#pragma unroll
            for (int q = 0; q < 4; ++q) acc[i][j][q] = 0.0f;

    const int T = K >> 6;

    auto loadT = [&](int t) {
        const int k0 = t << 6;
        if (!TRA) {
#pragma unroll
            for (int it = 0; it < 4; ++it) {
                int idx = tid + it * 256;
                int r = idx >> 4, q = (idx & 15) << 2;
                *(float4*)(aReg + it * 4) =
                    *(const float4*)(A + (size_t)(m0 + r) * lda + k0 + q);
            }
        } else {
            const int r = tid & 63, cb = (tid >> 6) << 4;
            const float* src = A + (size_t)(k0 + cb) * lda + m0 + r;
#pragma unroll
            for (int j = 0; j < 16; ++j) aReg[j] = src[(size_t)j * lda];
        }
        if (!TRB) {
#pragma unroll
            for (int it = 0; it < 8; ++it) {
                int idx = tid + it * 256;
                int r = idx >> 4, q = (idx & 15) << 2;
                *(float4*)(bReg + it * 4) =
                    *(const float4*)(B + (size_t)(n0 + r) * ldb + k0 + q);
            }
        } else {
            const int r = tid & 127, cb = (tid >> 7) << 5;
            const float* src = B + (size_t)(k0 + cb) * ldb + n0 + r;
#pragma unroll
            for (int j = 0; j < 32; ++j) bReg[j] = src[(size_t)j * ldb];
        }
    };

    auto storeT = [&](int st) {
        __nv_bfloat16* Ah = sm + st * STG_ELEMS;
        __nv_bfloat16* Am = Ah + 4608;
        __nv_bfloat16* Bh = Ah + 9216;
        __nv_bfloat16* Bm = Ah + 18432;
        if (!TRA) {
#pragma unroll
            for (int it = 0; it < 4; ++it) {
                int idx = tid + it * 256;
                int r = idx >> 4, q = (idx & 15) << 2;
                uint32_t hp[2], mp[2];
#pragma unroll
                for (int w = 0; w < 2; ++w) {
                    __nv_bfloat16 h0, h1, mq0, mq1;
                    split2(aReg[it * 4 + 2 * w], h0, mq0);
                    split2(aReg[it * 4 + 2 * w + 1], h1, mq1);
                    hp[w] = (uint32_t)__bfloat16_as_ushort(h0) |
                            ((uint32_t)__bfloat16_as_ushort(h1) << 16);
                    mp[w] = (uint32_t)__bfloat16_as_ushort(mq0) |
                            ((uint32_t)__bfloat16_as_ushort(mq1) << 16);
                }
                *(uint2*)(Ah + r * SMS + q) = make_uint2(hp[0], hp[1]);
                *(uint2*)(Am + r * SMS + q) = make_uint2(mp[0], mp[1]);
            }
        } else {
            const int r = tid & 63, cb = (tid >> 6) << 4;
#pragma unroll
            for (int j = 0; j < 16; ++j) {
                __nv_bfloat16 h, m;
                split2(aReg[j], h, m);
                Ah[r * SMS + cb + j] = h;
                Am[r * SMS + cb + j] = m;
            }
        }
        if (!TRB) {
#pragma unroll
            for (int it = 0; it < 8; ++it) {
                int idx = tid + it * 256;
                int r = idx >> 4, q = (idx & 15) << 2;
                uint32_t hp[2], mp[2];
#pragma unroll
                for (int w = 0; w < 2; ++w) {
                    __nv_bfloat16 h0, h1, mq0, mq1;
                    split2(bReg[it * 4 + 2 * w], h0, mq0);
                    split2(bReg[it * 4 + 2 * w + 1], h1, mq1);
                    hp[w] = (uint32_t)__bfloat16_as_ushort(h0) |
                            ((uint32_t)__bfloat16_as_ushort(h1) << 16);
                    mp[w] = (uint32_t)__bfloat16_as_ushort(mq0) |
                            ((uint32_t)__bfloat16_as_ushort(mq1) << 16);
                }
                *(uint2*)(Bh + r * SMS + q) = make_uint2(hp[0], hp[1]);
                *(uint2*)(Bm + r * SMS + q) = make_uint2(mp[0], mp[1]);
            }
        } else {
            const int r = tid & 127, cb = (tid >> 7) << 5;
#pragma unroll
            for (int j = 0; j < 32; ++j) {
                __nv_bfloat16 h, m;
                split2(bReg[j], h, m);
                Bh[r * SMS + cb + j] = h;
                Bm[r * SMS + cb + j] = m;
            }
        }
    };

    auto compute = [&](int st) {
        const __nv_bfloat16* base = sm + st * STG_ELEMS;
#pragma unroll
        for (int p = 0; p < 3; ++p) {
            const __nv_bfloat16* As = base + (p == 2 ? 4608 : 0);
            const __nv_bfloat16* Bs = base + (p == 1 ? 18432 : 9216);
#pragma unroll
            for (int kk = 0; kk < 4; ++kk) {
                uint32_t af[2][4], bf[4][2];
#pragma unroll
                for (int mt = 0; mt < 2; ++mt) {
                    const __nv_bfloat16* p0 =
                        As + (wy * 32 + mt * 16 + g) * SMS + kk * 16 + 2 * tg;
                    const __nv_bfloat16* p1 = p0 + 8 * SMS;
                    af[mt][0] = *(const uint32_t*)p0;
                    af[mt][1] = *(const uint32_t*)p1;
                    af[mt][2] = *(const uint32_t*)(p0 + 8);
                    af[mt][3] = *(const uint32_t*)(p1 + 8);
                }
#pragma unroll
                for (int nt = 0; nt < 4; ++nt) {
                    const __nv_bfloat16* p0 =
                        Bs + (wx * 32 + nt * 8 + g) * SMS + kk * 16 + 2 * tg;
                    bf[nt][0] = *(const uint32_t*)p0;
                    bf[nt][1] = *(const uint32_t*)(p0 + 8);
                }
#pragma unroll
                for (int mt = 0; mt < 2; ++mt)
#pragma unroll
                    for (int nt = 0; nt < 4; ++nt)
                        mma16816(acc[mt][nt], af[mt][0], af[mt][1], af[mt][2], af[mt][3],
                                 bf[nt][0], bf[nt][1]);
            }
        }
    };

    loadT(0);
    storeT(0);
    __syncthreads();
    for (int t = 0; t < T; ++t) {
        if (t + 1 < T) loadT(t + 1);
        compute(t & 1);
        if (t + 1 < T) storeT((t + 1) & 1);
        __syncthreads();
    }

#pragma unroll
    for (int mt = 0; mt < 2; ++mt) {
#pragma unroll
        for (int nt = 0; nt < 4; ++nt) {
#pragma unroll
            for (int half = 0; half < 2; ++half) {
                int r = m0 + wy * 32 + mt * 16 + g + half * 8;
                int c = n0 + wx * 32 + nt * 8 + 2 * tg;
                float v0 = alpha * acc[mt][nt][half * 2 + 0];
                float v1 = alpha * acc[mt][nt][half * 2 + 1];
                if (bias) { v0 += bias[c]; v1 += bias[c + 1]; }
                if (beta != 0.0f) {
                    v0 += beta * C[(size_t)r * ldc + c];
                    v1 += beta * C[(size_t)r * ldc + c + 1];
                }
                if (diagAdd != 0.0f) {
                    if (r == c) v0 += diagAdd;
                    if (r == c + 1) v1 += diagAdd;
                }
                if (flags & 1) { v0 = fmaxf(v0, 0.0f); v1 = fmaxf(v1, 0.0f); }
                *(float2*)(C + (size_t)r * ldc + c) = make_float2(v0, v1);
            }
        }
    }
}

// ================= potrf v2.5 (128x128 diag block) + diag-block inverse =================
// v2's proven distributed column loop, but: 2 barriers/column (rsqrtf broadcast, no
// tid0 sqrt chain; diag kept as running residual, sqrt'd in one parallel pass at end)
// and register-tiled bisection combines. Dinv -> Linv diag block (ld=ldd).
extern __shared__ float s_potrf[];
__global__ __launch_bounds__(256) void potrf_diag_kernel(float* A, int lda, int k,
                                                         float* Dv, int ldd) {
    float* sL = s_potrf;              // [128*129]
    float* sX = s_potrf + 128 * 129;  // [128*129]
    float* sc = sX + 128 * 129;       // [64*64] scratch
    const int tid = threadIdx.x, warp = tid >> 5, lane = tid & 31;
    float* Ab = A + (size_t)k * NB * lda + (size_t)k * NB;

    for (int idx = tid; idx < NB * NB; idx += 256) {
        int r = idx >> 7, c = idx & 127;
        sL[r * 129 + c] = Ab[(size_t)r * lda + c];
    }
    for (int idx = tid; idx < 128 * 129; idx += 256) sX[idx] = 0.0f;
    __syncthreads();

    for (int p = 0; p < 4; ++p) {
        const int pj = p * 32, pe = pj + 32;
        for (int j = pj; j < pe; ++j) {
            // diag is the running residual; everyone derives invd by broadcast read
            float invd = rsqrtf(sL[j * 129 + j]);
            for (int i = j + 1 + tid; i < 128; i += 256) sL[i * 129 + j] *= invd;
            __syncthreads();
            const int tx = tid & 7, ty = tid >> 3;
            for (int c = j + 1 + tx; c < pe; c += 8) {
                float lcj = sL[c * 129 + j];
                for (int i = c + ty; i < 128; i += 32)
                    sL[i * 129 + c] -= sL[i * 129 + j] * lcj;
            }
            __syncthreads();
        }
        // rank-32 trailing update (lower only, balanced) — residual diags included
        if (pe < 128) {
            const int rr = tid & 127, half = tid >> 7;
            if (rr < 128 - pe) {
                const int i = pe + rr;
                float a[32];
#pragma unroll
                for (int kk = 0; kk < 32; ++kk) a[kk] = sL[i * 129 + pj + kk];
                for (int c = pe + half; c <= i; c += 2) {
                    float s = 0.0f;
#pragma unroll
                    for (int kk = 0; kk < 32; ++kk) s += a[kk] * sL[c * 129 + pj + kk];
                    sL[i * 129 + c] -= s;
                }
            }
            __syncthreads();
        }
    }
    // one parallel pass: residual diag -> sqrt (the actual L diagonal)
    if (tid < 128) sL[tid * 129 + tid] = sqrtf(sL[tid * 129 + tid]);
    __syncthreads();

    // ---- Dinv = inv(L): 4 warp-local 32x32 inversions ----
    if (warp < 4) {
        const int b = warp * 32, c = lane;
        float x[32];
#pragma unroll
        for (int r = 0; r < 32; ++r) x[r] = 0.0f;
#pragma unroll
        for (int r = 0; r < 32; ++r) {
            if (r >= c) {
                float s = (r == c) ? 1.0f : 0.0f;
#pragma unroll
                for (int kk = 0; kk < 32; ++kk)
                    if (kk >= c && kk < r) s -= sL[(b + r) * 129 + b + kk] * x[kk];
                x[r] = s / sL[(b + r) * 129 + b + r];
            }
        }
#pragma unroll
        for (int r = 0; r < 32; ++r) sX[(b + r) * 129 + b + c] = x[r];
    }
    __syncthreads();
    // ---- combine 32 -> 64 (two pairs): X21 = -X22 * L21 * X11, register-tiled ----
    {
        const int p2 = tid >> 7, t = tid & 127;
        const int b = p2 * 64;
        float* tmp = sc + p2 * 1024;
        const int c = t & 31;
        const int r0 = t >> 5;  // 0..3
        float xcol[32];
#pragma unroll
        for (int kk = 0; kk < 32; ++kk) xcol[kk] = sX[(b + kk) * 129 + b + c];
#pragma unroll
        for (int q = 0; q < 8; ++q) {
            int r = r0 + q * 4;
            float s = 0.0f;
#pragma unroll
            for (int kk = 0; kk < 32; ++kk)
                s += sL[(b + 32 + r) * 129 + b + kk] * xcol[kk];
            tmp[r * 32 + c] = s;
        }
        __syncthreads();
        float tcol[32];
#pragma unroll
        for (int kk = 0; kk < 32; ++kk) tcol[kk] = tmp[kk * 32 + c];
#pragma unroll
        for (int q = 0; q < 8; ++q) {
            int r = r0 + q * 4;
            float s = 0.0f;
#pragma unroll
            for (int kk = 0; kk < 32; ++kk)
                s += sX[(b + 32 + r) * 129 + b + 32 + kk] * tcol[kk];
            sX[(b + 32 + r) * 129 + b + c] = -s;
        }
    }
    __syncthreads();
    // ---- combine 64 -> 128: X21 = -X22 * L21 * X11, register-tiled ----
    {
        const int c = tid & 63;
        const int r0 = tid >> 6;  // 0..3
        float acc[16];
#pragma unroll
        for (int q = 0; q < 16; ++q) acc[q] = 0.0f;
        for (int h = 0; h < 2; ++h) {
            float xcol[32];
#pragma unroll
            for (int kk = 0; kk < 32; ++kk) xcol[kk] = sX[(h * 32 + kk) * 129 + c];
#pragma unroll
            for (int q = 0; q < 16; ++q) {
                int r = r0 + q * 4;
                float s = acc[q];
#pragma unroll
                for (int kk = 0; kk < 32; ++kk)
                    s += sL[(64 + r) * 129 + h * 32 + kk] * xcol[kk];
                acc[q] = s;
            }
        }
#pragma unroll
        for (int q = 0; q < 16; ++q) sc[(r0 + q * 4) * 64 + c] = acc[q];
        __syncthreads();
#pragma unroll
        for (int q = 0; q < 16; ++q) acc[q] = 0.0f;
        for (int h = 0; h < 2; ++h) {
            float tcol[32];
#pragma unroll
            for (int kk = 0; kk < 32; ++kk) tcol[kk] = sc[(h * 32 + kk) * 64 + c];
#pragma unroll
            for (int q = 0; q < 16; ++q) {
                int r = r0 + q * 4;
                float s = acc[q];
#pragma unroll
                for (int kk = 0; kk < 32; ++kk)
                    s += sX[(64 + r) * 129 + 64 + h * 32 + kk] * tcol[kk];
                acc[q] = s;
            }
        }
#pragma unroll
        for (int q = 0; q < 16; ++q) sX[(64 + r0 + q * 4) * 129 + c] = -acc[q];
    }
    __syncthreads();
    // ---- write out: L (lower, zero upper) into A, Dinv into Linv diag block ----
    for (int idx = tid; idx < NB * NB; idx += 256) {
        int r = idx >> 7, c = idx & 127;
        Ab[(size_t)r * lda + c] = (c <= r) ? sL[r * 129 + c] : 0.0f;
        Dv[(size_t)r * ldd + c] = sX[r * 129 + c];
    }
}

// ================= small utility kernels =================
__global__ void transpose_kernel(const float* __restrict__ src, float* __restrict__ dst) {
    __shared__ float t[32][33];
    int bx = blockIdx.x * 32, by = blockIdx.y * 32;
    t[threadIdx.y][threadIdx.x] = src[(size_t)(by + threadIdx.y) * Nn + bx + threadIdx.x];
    __syncthreads();
    dst[(size_t)(bx + threadIdx.y) * Nn + by + threadIdx.x] = t[threadIdx.x][threadIdx.y];
}

// ================= host orchestration =================
template <int TRA, int TRB>
static void gm(const float* A, int lda, long long sA, const float* B, int ldb, long long sB,
               int K, float* C, int ldc, long long sC, int M, int N, const float* bias,
               float alpha, float beta, float dAdd, int flags, int batch) {
    gemm_mma<TRA, TRB><<<dim3(N / 128, M / 64, batch), 256, MMA_SMEM>>>(
        A, lda, sA, B, ldb, sB, K, C, ldc, sC, bias, alpha, beta, dAdd, flags);
}

static const int POTRF_SMEM = (2 * 128 * 129 + 64 * 64) * (int)sizeof(float);  // 148480

static void chol_inplace(float* A, float* Linv) {
    for (int k = 0; k < Nn / NB; ++k) {
        float* Dv = Linv + (size_t)k * NB * (Nn + 1);
        potrf_diag_kernel<<<1, 256, POTRF_SMEM>>>(A, Nn, k, Dv, Nn);
        int rem = Nn - (k + 1) * NB;
        if (rem > 0) {
            float* panel = A + (size_t)(k + 1) * NB * Nn + (size_t)k * NB;
            gm<0, 0>(panel, Nn, 0, Dv, Nn, 0, NB, panel, Nn, 0, rem, NB, nullptr, 1.0f,
                     0.0f, 0.0f, 0, 1);
            float* At = A + (size_t)(k + 1) * NB * Nn + (size_t)(k + 1) * NB;
            gm<0, 0>(panel, Nn, 0, panel, Nn, 0, NB, At, Nn, 0, rem, rem, nullptr, -1.0f,
                     1.0f, 0.0f, 2, 1);
        }
    }
}

static void build_linv(const float* A, float* Linv, float* tmp) {
    for (int s = 128; s <= 512; s <<= 1) {
        int P = Nn / (2 * s);
        long long str = 2LL * s * (Nn + 1);
        gm<0, 1>(A + (long long)s * Nn, Nn, str, Linv, Nn, str, s, tmp, s, (long long)s * s,
                 s, s, nullptr, 1.0f, 0.0f, 0.0f, 0, P);
        gm<0, 1>(Linv + (long long)s * (Nn + 1), Nn, str, tmp, s, (long long)s * s, s,
                 Linv + (long long)s * Nn, Nn, str, s, s, nullptr, -1.0f, 0.0f, 0.0f, 0, P);
    }
}

extern "C" void kernel_launch(void* const* d_in, const int* in_sizes, int n_in, void* d_out,
                              int out_size) {
    const float* x = (const float*)d_in[0];
    const float* Va = (const float*)d_in[1];
    const float* ba = (const float*)d_in[2];
    const float* Vin = (const float*)d_in[3];
    const float* bin = (const float*)d_in[4];
    const float* Vb = (const float*)d_in[5];
    float* out = (float*)d_out;

    float *dA, *dLinv, *dTmp, *dW, *dT, *dGamma, *dS, *dAw, *dCur, *dCur2;
    cudaGetSymbolAddress((void**)&dA, g_A);
    cudaGetSymbolAddress((void**)&dLinv, g_Linv);
    cudaGetSymbolAddress((void**)&dTmp, g_tmp);
    cudaGetSymbolAddress((void**)&dW, g_W);
    cudaGetSymbolAddress((void**)&dT, g_T);
    cudaGetSymbolAddress((void**)&dGamma, g_gamma);
    cudaGetSymbolAddress((void**)&dS, g_S);
    cudaGetSymbolAddress((void**)&dAw, g_aw);
    cudaGetSymbolAddress((void**)&dCur, g_cur);
    cudaGetSymbolAddress((void**)&dCur2, g_cur2);
    cudaFuncSetAttribute(potrf_diag_kernel, cudaFuncAttributeMaxDynamicSharedMemorySize,
                         POTRF_SMEM);
    cudaFuncSetAttribute(gemm_mma<0, 0>, cudaFuncAttributeMaxDynamicSharedMemorySize,
                         MMA_SMEM);
    cudaFuncSetAttribute(gemm_mma<0, 1>, cudaFuncAttributeMaxDynamicSharedMemorySize,
                         MMA_SMEM);
    cudaFuncSetAttribute(gemm_mma<1, 1>, cudaFuncAttributeMaxDynamicSharedMemorySize,
                         MMA_SMEM);

    // zero Linv each call (also shifts the ncu -s5 window onto the chol chain)
    cudaMemsetAsync(dLinv, 0, (size_t)Nn * Nn * sizeof(float));

    // ---- Layer A: M = I + Va^T Va ; factor ; Linv ; a_weight = Va Linv^T ----
    gm<1, 1>(Va, Nn, 0, Va, Nn, 0, Nn, dA, Nn, 0, Nn, Nn, nullptr, 1.0f, 0.0f, 1.0f, 2, 1);
    chol_inplace(dA, dLinv);
    build_linv(dA, dLinv, dTmp);
    gm<0, 0>(Va, Nn, 0, dLinv, Nn, 0, Nn, dAw, Nn, 0, Nn, Nn, nullptr, 1.0f, 0.0f, 0.0f, 0, 1);

    // first = x @ a_weight^T + ba -> out
    gm<0, 0>(x, Nn, 0, dAw, Nn, 0, Nn, out, Nn, 0, BATCH, Nn, ba, 1.0f, 0.0f, 0.0f, 0, 1);
    cudaMemcpyAsync(dCur, x, (size_t)BATCH * Nn * sizeof(float), cudaMemcpyDeviceToDevice);

    float* cur = dCur;
    float* cur2 = dCur2;
    for (int i = 0; i < NL; ++i) {
        // T = gamma @ Linv^T  (layer 0: gamma = I -> T = Linv^T)
        if (i == 0)
            transpose_kernel<<<dim3(32, 32), dim3(32, 32)>>>(dLinv, dT);
        else
            gm<0, 0>(dGamma, Nn, 0, dLinv, Nn, 0, Nn, dT, Nn, 0, Nn, Nn, nullptr, 1.0f,
                     0.0f, 0.0f, 0, 1);
        // W = V_i @ Linv^T
        gm<0, 0>(Vin + (size_t)i * Nn * Nn, Nn, 0, dLinv, Nn, 0, Nn, dW, Nn, 0, Nn, Nn,
                 nullptr, 1.0f, 0.0f, 0.0f, 0, 1);
        // cur = relu(cur @ W^T + b_i)
        gm<0, 0>(cur, Nn, 0, dW, Nn, 0, Nn, cur2, Nn, 0, BATCH, Nn, bin + (size_t)i * Nn,
                 1.0f, 0.0f, 0.0f, 1, 1);
        { float* t = cur; cur = cur2; cur2 = t; }
        // S += T T^T (symmetric accumulator; replaces per-layer sigma choleskys)
        gm<0, 0>(dT, Nn, 0, dT, Nn, 0, Nn, dS, Nn, 0, Nn, Nn, nullptr, 1.0f,
                 (i == 0) ? 0.0f : 1.0f, 0.0f, 0, 1);
        // gamma = T @ W^T
        gm<0, 0>(dT, Nn, 0, dW, Nn, 0, Nn, dGamma, Nn, 0, Nn, Nn, nullptr, 1.0f, 0.0f,
                 0.0f, 0, 1);
        // M = I + 0.5 W W^T ; factor ; Linv
        gm<0, 0>(dW, Nn, 0, dW, Nn, 0, Nn, dA, Nn, 0, Nn, Nn, nullptr, 0.5f, 0.0f, 1.0f, 2, 1);
        chol_inplace(dA, dLinv);
        build_linv(dA, dLinv, dTmp);
    }

    // ---- Final layer B ----
    gm<0, 0>(Vb, Nn, 0, dLinv, Nn, 0, Nn, dGamma, Nn, 0, Nn, Nn, nullptr, 1.0f, 0.0f, 0.0f, 0, 1);
    gm<0, 0>(dAw, Nn, 0, dS, Nn, 0, Nn, dT, Nn, 0, Nn, Nn, nullptr, 1.0f, 0.0f, 0.0f, 0, 1);
    gm<0, 0>(dT, Nn, 0, dAw, Nn, 0, Nn, dA, Nn, 0, Nn, Nn, nullptr, 1.0f, 0.0f, 1.0f, 2, 1);
    chol_inplace(dA, dLinv);
    build_linv(dA, dLinv, dTmp);
    gm<1, 1>(dLinv, Nn, 0, dGamma, Nn, 0, Nn, dW, Nn, 0, Nn, Nn, nullptr, 1.0f, 0.0f, 0.0f, 0, 1);
    gm<0, 0>(cur, Nn, 0, dW, Nn, 0, Nn, out, Nn, 0, BATCH, Nn, nullptr, 1.0f, 1.0f, 0.0f, 0, 1);
}

// round 17
// speedup vs baseline: 1.1972x; 1.0575x over previous
#include <cuda_runtime.h>
#include <cuda_bf16.h>
#include <cstdint>
#include <cstddef>

#define Nn 1024
#define BATCH 4096
#define NL 8
#define NB 128
#define CHB 112

// ---------------- device scratch (no allocations allowed) ----------------
__device__ float g_A[Nn * Nn];
__device__ float g_Linv[Nn * Nn];
__device__ float g_tmp[Nn * Nn];
__device__ float g_W[Nn * Nn];
__device__ float g_T[Nn * Nn];
__device__ float g_gamma[Nn * Nn];
__device__ float g_S[Nn * Nn];
__device__ float g_aw[Nn * Nn];
__device__ float g_cur[BATCH * Nn];
__device__ float g_cur2[BATCH * Nn];
__device__ int g_barC = 0, g_barG = 0;

// ================= bf16x3-split GEMM pieces =================
#define SMS 72
#define STG_ELEMS 27648
static const int MMA_SMEM = 2 * STG_ELEMS * (int)sizeof(__nv_bfloat16);  // 110592

__device__ __forceinline__ void mma16816(float* c, uint32_t a0, uint32_t a1, uint32_t a2,
                                         uint32_t a3, uint32_t b0, uint32_t b1) {
    asm volatile(
        "mma.sync.aligned.m16n8k16.row.col.f32.bf16.bf16.f32 "
        "{%0,%1,%2,%3},{%4,%5,%6,%7},{%8,%9},{%0,%1,%2,%3};\n"
        : "+f"(c[0]), "+f"(c[1]), "+f"(c[2]), "+f"(c[3])
        : "r"(a0), "r"(a1), "r"(a2), "r"(a3), "r"(b0), "r"(b1));
}

__device__ __forceinline__ void split2(float v, __nv_bfloat16& h, __nv_bfloat16& m) {
    h = __float2bfloat16(v);
    m = __float2bfloat16(v - __bfloat162float(h));
}

// ---------- standalone pipelined GEMM kernel (big matmuls) ----------
template <int TRA, int TRB>
__global__ __launch_bounds__(256, 2) void gemm_mma(
    const float* __restrict__ A, int lda, long long strA, const float* __restrict__ B,
    int ldb, long long strB, int K, float* __restrict__ C, int ldc, long long strC,
    const float* __restrict__ bias, float alpha, float beta, float diagAdd, int flags) {
    const int bi = blockIdx.y, bj = blockIdx.x;
    if ((flags & 2) && 2 * bj > bi) return;
    A += (long long)blockIdx.z * strA;
    B += (long long)blockIdx.z * strB;
    C += (long long)blockIdx.z * strC;
    extern __shared__ __nv_bfloat16 sm[];
    const int tid = threadIdx.x, wid = tid >> 5, lane = tid & 31;
    const int wy = wid >> 2, wx = wid & 3;
    const int g = lane >> 2, tg = lane & 3;
    const int m0 = bi * 64, n0 = bj * 128;

    float aReg[16], bReg[32];
    float acc[2][4][4];
#pragma unroll
    for (int i = 0; i < 2; ++i)
#pragma unroll
        for (int j = 0; j < 4; ++j)
#pragma unroll
            for (int q = 0; q < 4; ++q) acc[i][j][q] = 0.0f;

    const int T = K >> 6;

    auto loadT = [&](int t) {
        const int k0 = t << 6;
        if (!TRA) {
#pragma unroll
            for (int it = 0; it < 4; ++it) {
                int idx = tid + it * 256;
                int r = idx >> 4, q = (idx & 15) << 2;
                *(float4*)(aReg + it * 4) =
                    *(const float4*)(A + (size_t)(m0 + r) * lda + k0 + q);
            }
        } else {
            const int r = tid & 63, cb = (tid >> 6) << 4;
            const float* src = A + (size_t)(k0 + cb) * lda + m0 + r;
#pragma unroll
            for (int j = 0; j < 16; ++j) aReg[j] = src[(size_t)j * lda];
        }
        if (!TRB) {
#pragma unroll
            for (int it = 0; it < 8; ++it) {
                int idx = tid + it * 256;
                int r = idx >> 4, q = (idx & 15) << 2;
                *(float4*)(bReg + it * 4) =
                    *(const float4*)(B + (size_t)(n0 + r) * ldb + k0 + q);
            }
        } else {
            const int r = tid & 127, cb = (tid >> 7) << 5;
            const float* src = B + (size_t)(k0 + cb) * ldb + n0 + r;
#pragma unroll
            for (int j = 0; j < 32; ++j) bReg[j] = src[(size_t)j * ldb];
        }
    };

    auto storeT = [&](int st) {
        __nv_bfloat16* Ah = sm + st * STG_ELEMS;
        __nv_bfloat16* Am = Ah + 4608;
        __nv_bfloat16* Bh = Ah + 9216;
        __nv_bfloat16* Bm = Ah + 18432;
        if (!TRA) {
#pragma unroll
            for (int it = 0; it < 4; ++it) {
                int idx = tid + it * 256;
                int r = idx >> 4, q = (idx & 15) << 2;
                uint32_t hp[2], mp[2];
#pragma unroll
                for (int w = 0; w < 2; ++w) {
                    __nv_bfloat16 h0, h1, mq0, mq1;
                    split2(aReg[it * 4 + 2 * w], h0, mq0);
                    split2(aReg[it * 4 + 2 * w + 1], h1, mq1);
                    hp[w] = (uint32_t)__bfloat16_as_ushort(h0) |
                            ((uint32_t)__bfloat16_as_ushort(h1) << 16);
                    mp[w] = (uint32_t)__bfloat16_as_ushort(mq0) |
                            ((uint32_t)__bfloat16_as_ushort(mq1) << 16);
                }
                *(uint2*)(Ah + r * SMS + q) = make_uint2(hp[0], hp[1]);
                *(uint2*)(Am + r * SMS + q) = make_uint2(mp[0], mp[1]);
            }
        } else {
            const int r = tid & 63, cb = (tid >> 6) << 4;
#pragma unroll
            for (int j = 0; j < 16; ++j) {
                __nv_bfloat16 h, m;
                split2(aReg[j], h, m);
                Ah[r * SMS + cb + j] = h;
                Am[r * SMS + cb + j] = m;
            }
        }
        if (!TRB) {
#pragma unroll
            for (int it = 0; it < 8; ++it) {
                int idx = tid + it * 256;
                int r = idx >> 4, q = (idx & 15) << 2;
                uint32_t hp[2], mp[2];
#pragma unroll
                for (int w = 0; w < 2; ++w) {
                    __nv_bfloat16 h0, h1, mq0, mq1;
                    split2(bReg[it * 4 + 2 * w], h0, mq0);
                    split2(bReg[it * 4 + 2 * w + 1], h1, mq1);
                    hp[w] = (uint32_t)__bfloat16_as_ushort(h0) |
                            ((uint32_t)__bfloat16_as_ushort(h1) << 16);
                    mp[w] = (uint32_t)__bfloat16_as_ushort(mq0) |
                            ((uint32_t)__bfloat16_as_ushort(mq1) << 16);
                }
                *(uint2*)(Bh + r * SMS + q) = make_uint2(hp[0], hp[1]);
                *(uint2*)(Bm + r * SMS + q) = make_uint2(mp[0], mp[1]);
            }
        } else {
            const int r = tid & 127, cb = (tid >> 7) << 5;
#pragma unroll
            for (int j = 0; j < 32; ++j) {
                __nv_bfloat16 h, m;
                split2(bReg[j], h, m);
                Bh[r * SMS + cb + j] = h;
                Bm[r * SMS + cb + j] = m;
            }
        }
    };

    auto compute = [&](int st) {
        const __nv_bfloat16* base = sm + st * STG_ELEMS;
#pragma unroll
        for (int p = 0; p < 3; ++p) {
            const __nv_bfloat16* As = base + (p == 2 ? 4608 : 0);
            const __nv_bfloat16* Bs = base + (p == 1 ? 18432 : 9216);
#pragma unroll
            for (int kk = 0; kk < 4; ++kk) {
                uint32_t af[2][4], bf[4][2];
#pragma unroll
                for (int mt = 0; mt < 2; ++mt) {
                    const __nv_bfloat16* p0 =
                        As + (wy * 32 + mt * 16 + g) * SMS + kk * 16 + 2 * tg;
                    const __nv_bfloat16* p1 = p0 + 8 * SMS;
                    af[mt][0] = *(const uint32_t*)p0;
                    af[mt][1] = *(const uint32_t*)p1;
                    af[mt][2] = *(const uint32_t*)(p0 + 8);
                    af[mt][3] = *(const uint32_t*)(p1 + 8);
                }
#pragma unroll
                for (int nt = 0; nt < 4; ++nt) {
                    const __nv_bfloat16* p0 =
                        Bs + (wx * 32 + nt * 8 + g) * SMS + kk * 16 + 2 * tg;
                    bf[nt][0] = *(const uint32_t*)p0;
                    bf[nt][1] = *(const uint32_t*)(p0 + 8);
                }
#pragma unroll
                for (int mt = 0; mt < 2; ++mt)
#pragma unroll
                    for (int nt = 0; nt < 4; ++nt)
                        mma16816(acc[mt][nt], af[mt][0], af[mt][1], af[mt][2], af[mt][3],
                                 bf[nt][0], bf[nt][1]);
            }
        }
    };

    loadT(0);
    storeT(0);
    __syncthreads();
    for (int t = 0; t < T; ++t) {
        if (t + 1 < T) loadT(t + 1);
        compute(t & 1);
        if (t + 1 < T) storeT((t + 1) & 1);
        __syncthreads();
    }

#pragma unroll
    for (int mt = 0; mt < 2; ++mt) {
#pragma unroll
        for (int nt = 0; nt < 4; ++nt) {
#pragma unroll
            for (int half = 0; half < 2; ++half) {
                int r = m0 + wy * 32 + mt * 16 + g + half * 8;
                int c = n0 + wx * 32 + nt * 8 + 2 * tg;
                float v0 = alpha * acc[mt][nt][half * 2 + 0];
                float v1 = alpha * acc[mt][nt][half * 2 + 1];
                if (bias) { v0 += bias[c]; v1 += bias[c + 1]; }
                if (beta != 0.0f) {
                    v0 += beta * C[(size_t)r * ldc + c];
                    v1 += beta * C[(size_t)r * ldc + c + 1];
                }
                if (diagAdd != 0.0f) {
                    if (r == c) v0 += diagAdd;
                    if (r == c + 1) v1 += diagAdd;
                }
                if (flags & 1) { v0 = fmaxf(v0, 0.0f); v1 = fmaxf(v1, 0.0f); }
                *(float2*)(C + (size_t)r * ldc + c) = make_float2(v0, v1);
            }
        }
    }
}

// ---------- same tile as a device function (for the fused chol kernel) ----------
template <int TRB>
__device__ void gemm_tile_dev(const float* __restrict__ A, int lda,
                              const float* __restrict__ B, int ldb, int K,
                              float* __restrict__ C, int ldc, float alpha, float beta,
                              int m0, int n0, __nv_bfloat16* sm) {
    const int tid = threadIdx.x, wid = tid >> 5, lane = tid & 31;
    const int wy = wid >> 2, wx = wid & 3;
    const int g = lane >> 2, tg = lane & 3;
    __syncthreads();  // protect smem reuse across phases/tiles

    float aReg[16], bReg[32];
    float acc[2][4][4];
#pragma unroll
    for (int i = 0; i < 2; ++i)
#pragma unroll
        for (int j = 0; j < 4; ++j)
#pragma unroll
            for (int q = 0; q < 4; ++q) acc[i][j][q] = 0.0f;

    const int T = K >> 6;

    auto loadT = [&](int t) {
        const int k0 = t << 6;
#pragma unroll
        for (int it = 0; it < 4; ++it) {
            int idx = tid + it * 256;
            int r = idx >> 4, q = (idx & 15) << 2;
            *(float4*)(aReg + it * 4) = *(const float4*)(A + (size_t)(m0 + r) * lda + k0 + q);
        }
        if (!TRB) {
#pragma unroll
            for (int it = 0; it < 8; ++it) {
                int idx = tid + it * 256;
                int r = idx >> 4, q = (idx & 15) << 2;
                *(float4*)(bReg + it * 4) =
                    *(const float4*)(B + (size_t)(n0 + r) * ldb + k0 + q);
            }
        } else {
            const int r = tid & 127, cb = (tid >> 7) << 5;
            const float* src = B + (size_t)(k0 + cb) * ldb + n0 + r;
#pragma unroll
            for (int j = 0; j < 32; ++j) bReg[j] = src[(size_t)j * ldb];
        }
    };

    auto storeT = [&](int st) {
        __nv_bfloat16* Ah = sm + st * STG_ELEMS;
        __nv_bfloat16* Am = Ah + 4608;
        __nv_bfloat16* Bh = Ah + 9216;
        __nv_bfloat16* Bm = Ah + 18432;
#pragma unroll
        for (int it = 0; it < 4; ++it) {
            int idx = tid + it * 256;
            int r = idx >> 4, q = (idx & 15) << 2;
            uint32_t hp[2], mp[2];
#pragma unroll
            for (int w = 0; w < 2; ++w) {
                __nv_bfloat16 h0, h1, mq0, mq1;
                split2(aReg[it * 4 + 2 * w], h0, mq0);
                split2(aReg[it * 4 + 2 * w + 1], h1, mq1);
                hp[w] = (uint32_t)__bfloat16_as_ushort(h0) |
                        ((uint32_t)__bfloat16_as_ushort(h1) << 16);
                mp[w] = (uint32_t)__bfloat16_as_ushort(mq0) |
                        ((uint32_t)__bfloat16_as_ushort(mq1) << 16);
            }
            *(uint2*)(Ah + r * SMS + q) = make_uint2(hp[0], hp[1]);
            *(uint2*)(Am + r * SMS + q) = make_uint2(mp[0], mp[1]);
        }
        if (!TRB) {
#pragma unroll
            for (int it = 0; it < 8; ++it) {
                int idx = tid + it * 256;
                int r = idx >> 4, q = (idx & 15) << 2;
                uint32_t hp[2], mp[2];
#pragma unroll
                for (int w = 0; w < 2; ++w) {
                    __nv_bfloat16 h0, h1, mq0, mq1;
                    split2(bReg[it * 4 + 2 * w], h0, mq0);
                    split2(bReg[it * 4 + 2 * w + 1], h1, mq1);
                    hp[w] = (uint32_t)__bfloat16_as_ushort(h0) |
                            ((uint32_t)__bfloat16_as_ushort(h1) << 16);
                    mp[w] = (uint32_t)__bfloat16_as_ushort(mq0) |
                            ((uint32_t)__bfloat16_as_ushort(mq1) << 16);
                }
                *(uint2*)(Bh + r * SMS + q) = make_uint2(hp[0], hp[1]);
                *(uint2*)(Bm + r * SMS + q) = make_uint2(mp[0], mp[1]);
            }
        } else {
            const int r = tid & 127, cb = (tid >> 7) << 5;
#pragma unroll
            for (int j = 0; j < 32; ++j) {
                __nv_bfloat16 h, m;
                split2(bReg[j], h, m);
                Bh[r * SMS + cb + j] = h;
                Bm[r * SMS + cb + j] = m;
            }
        }
    };

    auto compute = [&](int st) {
        const __nv_bfloat16* base = sm + st * STG_ELEMS;
#pragma unroll
        for (int p = 0; p < 3; ++p) {
            const __nv_bfloat16* As = base + (p == 2 ? 4608 : 0);
            const __nv_bfloat16* Bs = base + (p == 1 ? 18432 : 9216);
#pragma unroll
            for (int kk = 0; kk < 4; ++kk) {
                uint32_t af[2][4], bf[4][2];
#pragma unroll
                for (int mt = 0; mt < 2; ++mt) {
                    const __nv_bfloat16* p0 =
                        As + (wy * 32 + mt * 16 + g) * SMS + kk * 16 + 2 * tg;
                    const __nv_bfloat16* p1 = p0 + 8 * SMS;
                    af[mt][0] = *(const uint32_t*)p0;
                    af[mt][1] = *(const uint32_t*)p1;
                    af[mt][2] = *(const uint32_t*)(p0 + 8);
                    af[mt][3] = *(const uint32_t*)(p1 + 8);
                }
#pragma unroll
                for (int nt = 0; nt < 4; ++nt) {
                    const __nv_bfloat16* p0 =
                        Bs + (wx * 32 + nt * 8 + g) * SMS + kk * 16 + 2 * tg;
                    bf[nt][0] = *(const uint32_t*)p0;
                    bf[nt][1] = *(const uint32_t*)(p0 + 8);
                }
#pragma unroll
                for (int mt = 0; mt < 2; ++mt)
#pragma unroll
                    for (int nt = 0; nt < 4; ++nt)
                        mma16816(acc[mt][nt], af[mt][0], af[mt][1], af[mt][2], af[mt][3],
                                 bf[nt][0], bf[nt][1]);
            }
        }
    };

    loadT(0);
    storeT(0);
    __syncthreads();
    for (int t = 0; t < T; ++t) {
        if (t + 1 < T) loadT(t + 1);
        compute(t & 1);
        if (t + 1 < T) storeT((t + 1) & 1);
        __syncthreads();
    }

#pragma unroll
    for (int mt = 0; mt < 2; ++mt) {
#pragma unroll
        for (int nt = 0; nt < 4; ++nt) {
#pragma unroll
            for (int half = 0; half < 2; ++half) {
                int r = m0 + wy * 32 + mt * 16 + g + half * 8;
                int c = n0 + wx * 32 + nt * 8 + 2 * tg;
                float v0 = alpha * acc[mt][nt][half * 2 + 0];
                float v1 = alpha * acc[mt][nt][half * 2 + 1];
                if (beta != 0.0f) {
                    v0 += beta * C[(size_t)r * ldc + c];
                    v1 += beta * C[(size_t)r * ldc + c + 1];
                }
                *(float2*)(C + (size_t)r * ldc + c) = make_float2(v0, v1);
            }
        }
    }
}

// ================= fused Cholesky + Linv (ONE launch) =================
__device__ __forceinline__ void grid_bar() {
    __threadfence();
    __syncthreads();
    if (threadIdx.x == 0) {
        volatile int* vg = &g_barG;
        int gen = *vg;
        if (atomicAdd(&g_barC, 1) == CHB - 1) {
            g_barC = 0;
            __threadfence();
            *vg = gen + 1;
        } else {
            int spins = 0;
            while (*vg == gen) {
                if (++spins > (1 << 14)) { __nanosleep(32); spins = 0; }
            }
        }
        __threadfence();
    }
    __syncthreads();
}

// R8-proven potrf v2: 32-col panels, 3 barriers/column, balanced rank-32 trailing,
// warp-local 32x32 inversions + 2 bisection combines. Dinv -> Linv diag (ld=Nn).
__device__ void potrf_dev(float* A, int k, float* Linv, float* sL, float* sX, float* sc) {
    const int tid = threadIdx.x;
    float* Ab = A + (size_t)k * NB * Nn + (size_t)k * NB;
    float* Dv = Linv + (size_t)k * NB * Nn + (size_t)k * NB;

    for (int idx = tid; idx < NB * NB; idx += 256) {
        int r = idx >> 7, c = idx & 127;
        sL[r * 129 + c] = Ab[(size_t)r * Nn + c];
    }
    for (int idx = tid; idx < 128 * 129; idx += 256) sX[idx] = 0.0f;
    __syncthreads();

    for (int p = 0; p < 4; ++p) {
        const int pj = p * 32, pe = pj + 32;
        for (int j = pj; j < pe; ++j) {
            if (tid == 0) sL[j * 129 + j] = sqrtf(sL[j * 129 + j]);
            __syncthreads();
            float invd = 1.0f / sL[j * 129 + j];
            for (int i = j + 1 + tid; i < 128; i += 256) sL[i * 129 + j] *= invd;
            __syncthreads();
            const int tx = tid & 7, ty = tid >> 3;
            for (int c = j + 1 + tx; c < pe; c += 8) {
                float lcj = sL[c * 129 + j];
                for (int i = c + ty; i < 128; i += 32)
                    sL[i * 129 + c] -= sL[i * 129 + j] * lcj;
            }
            __syncthreads();
        }
        if (pe < 128) {
            const int rr = tid & 127, half = tid >> 7;
            if (rr < 128 - pe) {
                const int i = pe + rr;
                float a[32];
#pragma unroll
                for (int kk = 0; kk < 32; ++kk) a[kk] = sL[i * 129 + pj + kk];
                for (int c = pe + half; c <= i; c += 2) {
                    float s = 0.0f;
#pragma unroll
                    for (int kk = 0; kk < 32; ++kk) s += a[kk] * sL[c * 129 + pj + kk];
                    sL[i * 129 + c] -= s;
                }
            }
            __syncthreads();
        }
    }

    const int warp = tid >> 5, lane = tid & 31;
    if (warp < 4) {
        const int b = warp * 32, c = lane;
        float x[32];
#pragma unroll
        for (int r = 0; r < 32; ++r) x[r] = 0.0f;
#pragma unroll
        for (int r = 0; r < 32; ++r) {
            if (r >= c) {
                float s = (r == c) ? 1.0f : 0.0f;
#pragma unroll
                for (int kk = 0; kk < 32; ++kk)
                    if (kk >= c && kk < r) s -= sL[(b + r) * 129 + b + kk] * x[kk];
                x[r] = s / sL[(b + r) * 129 + b + r];
            }
        }
#pragma unroll
        for (int r = 0; r < 32; ++r) sX[(b + r) * 129 + b + c] = x[r];
    }
    __syncthreads();
    {
        const int p2 = tid >> 7, t = tid & 127;
        const int b = p2 * 64;
        float* tmp = sc + p2 * 1024;
#pragma unroll
        for (int q = 0; q < 8; ++q) {
            int idx = t + q * 128;
            int r = idx >> 5, c = idx & 31;
            float s = 0.0f;
#pragma unroll
            for (int kk = 0; kk < 32; ++kk)
                s += sL[(b + 32 + r) * 129 + b + kk] * sX[(b + kk) * 129 + b + c];
            tmp[r * 32 + c] = s;
        }
        __syncthreads();
#pragma unroll
        for (int q = 0; q < 8; ++q) {
            int idx = t + q * 128;
            int r = idx >> 5, c = idx & 31;
            float s = 0.0f;
#pragma unroll
            for (int kk = 0; kk < 32; ++kk)
                s += sX[(b + 32 + r) * 129 + b + 32 + kk] * tmp[kk * 32 + c];
            sX[(b + 32 + r) * 129 + b + c] = -s;
        }
    }
    __syncthreads();
    {
#pragma unroll
        for (int q = 0; q < 16; ++q) {
            int idx = tid + q * 256;
            int r = idx >> 6, c = idx & 63;
            float s = 0.0f;
            for (int kk = 0; kk < 64; ++kk)
                s += sL[(64 + r) * 129 + kk] * sX[kk * 129 + c];
            sc[r * 64 + c] = s;
        }
        __syncthreads();
#pragma unroll
        for (int q = 0; q < 16; ++q) {
            int idx = tid + q * 256;
            int r = idx >> 6, c = idx & 63;
            float s = 0.0f;
            for (int kk = 0; kk < 64; ++kk)
                s += sX[(64 + r) * 129 + 64 + kk] * sc[kk * 64 + c];
            sX[(64 + r) * 129 + c] = -s;
        }
    }
    __syncthreads();
    for (int idx = tid; idx < NB * NB; idx += 256) {
        int r = idx >> 7, c = idx & 127;
        Ab[(size_t)r * Nn + c] = (c <= r) ? sL[r * 129 + c] : 0.0f;
        Dv[(size_t)r * Nn + c] = sX[r * 129 + c];
    }
}

static const int FUSED_SMEM = (2 * 128 * 129 + 64 * 64) * (int)sizeof(float);  // 148480

extern __shared__ float s_fused[];
__global__ __launch_bounds__(256) void chol_linv_fused(float* A, float* Linv, float* tmp) {
    float* sL = s_fused;
    float* sX = s_fused + 128 * 129;
    float* sc = sX + 128 * 129;
    __nv_bfloat16* smb = (__nv_bfloat16*)s_fused;
    const int bid = blockIdx.x;

    if (bid == 0) potrf_dev(A, 0, Linv, sL, sX, sc);
    grid_bar();

    for (int k = 0; k < 7; ++k) {
        const int base = (k + 1) * NB, rem = Nn - base;
        const int nrt = rem >> 6, nct = rem >> 7;
        float* panel = A + (size_t)base * Nn + (size_t)k * NB;
        const float* Dv = Linv + (size_t)k * NB * (Nn + 1);
        // ---- trsm: panel := panel * Dinv^T (tensor-core tiles, in place) ----
        for (int t = bid; t < nrt; t += CHB)
            gemm_tile_dev<0>(panel, Nn, Dv, Nn, 128, panel, Nn, 1.0f, 0.0f, t * 64, 0, smb);
        grid_bar();
        // ---- syrk: trailing -= panel*panel^T (lower tiles) + lookahead potrf ----
        float* Ct = A + (size_t)base * Nn + base;
        if (bid == 0) {
            gemm_tile_dev<0>(panel, Nn, panel, Nn, 128, Ct, Nn, -1.0f, 1.0f, 0, 0, smb);
            gemm_tile_dev<0>(panel, Nn, panel, Nn, 128, Ct, Nn, -1.0f, 1.0f, 64, 0, smb);
            __syncthreads();
            potrf_dev(A, k + 1, Linv, sL, sX, sc);
        } else {
            for (int idx = bid - 1; idx < nrt * nct; idx += CHB - 1) {
                int ti = idx % nrt, tj = idx / nrt;
                if (2 * tj > ti) continue;
                if (tj == 0 && ti < 2) continue;  // next-diag tiles done by block 0
                gemm_tile_dev<0>(panel, Nn, panel, Nn, 128, Ct, Nn, -1.0f, 1.0f, ti * 64,
                                 tj * 128, smb);
            }
        }
        grid_bar();
    }

    // ---- block-bisection inverse (diag inverses already in Linv) ----
    for (int s = 128; s <= 512; s <<= 1) {
        const int P = Nn / (2 * s), rt = s >> 6, ct = s >> 7, tot = P * rt * ct;
        const long long str = 2LL * s * (Nn + 1);
        for (int idx = bid; idx < tot; idx += CHB) {
            int p = idx / (rt * ct), r2 = idx % (rt * ct), ti = r2 / ct, tj = r2 % ct;
            gemm_tile_dev<1>(A + (size_t)s * Nn + p * str, Nn, Linv + p * str, Nn, s,
                             tmp + (size_t)p * s * s, s, 1.0f, 0.0f, ti * 64, tj * 128, smb);
        }
        grid_bar();
        for (int idx = bid; idx < tot; idx += CHB) {
            int p = idx / (rt * ct), r2 = idx % (rt * ct), ti = r2 / ct, tj = r2 % ct;
            gemm_tile_dev<1>(Linv + (size_t)s * (Nn + 1) + p * str, Nn,
                             tmp + (size_t)p * s * s, s, s, Linv + (size_t)s * Nn + p * str,
                             Nn, -1.0f, 0.0f, ti * 64, tj * 128, smb);
        }
        grid_bar();
    }
}

// ================= small utility kernels =================
__global__ void transpose_kernel(const float* __restrict__ src, float* __restrict__ dst) {
    __shared__ float t[32][33];
    int bx = blockIdx.x * 32, by = blockIdx.y * 32;
    t[threadIdx.y][threadIdx.x] = src[(size_t)(by + threadIdx.y) * Nn + bx + threadIdx.x];
    __syncthreads();
    dst[(size_t)(bx + threadIdx.y) * Nn + by + threadIdx.x] = t[threadIdx.x][threadIdx.y];
}

// ================= host orchestration =================
template <int TRA, int TRB>
static void gm(const float* A, int lda, long long sA, const float* B, int ldb, long long sB,
               int K, float* C, int ldc, long long sC, int M, int N, const float* bias,
               float alpha, float beta, float dAdd, int flags, int batch) {
    gemm_mma<TRA, TRB><<<dim3(N / 128, M / 64, batch), 256, MMA_SMEM>>>(
        A, lda, sA, B, ldb, sB, K, C, ldc, sC, bias, alpha, beta, dAdd, flags);
}

extern "C" void kernel_launch(void* const* d_in, const int* in_sizes, int n_in, void* d_out,
                              int out_size) {
    const float* x = (const float*)d_in[0];
    const float* Va = (const float*)d_in[1];
    const float* ba = (const float*)d_in[2];
    const float* Vin = (const float*)d_in[3];
    const float* bin = (const float*)d_in[4];
    const float* Vb = (const float*)d_in[5];
    float* out = (float*)d_out;

    float *dA, *dLinv, *dTmp, *dW, *dT, *dGamma, *dS, *dAw, *dCur, *dCur2;
    cudaGetSymbolAddress((void**)&dA, g_A);
    cudaGetSymbolAddress((void**)&dLinv, g_Linv);
    cudaGetSymbolAddress((void**)&dTmp, g_tmp);
    cudaGetSymbolAddress((void**)&dW, g_W);
    cudaGetSymbolAddress((void**)&dT, g_T);
    cudaGetSymbolAddress((void**)&dGamma, g_gamma);
    cudaGetSymbolAddress((void**)&dS, g_S);
    cudaGetSymbolAddress((void**)&dAw, g_aw);
    cudaGetSymbolAddress((void**)&dCur, g_cur);
    cudaGetSymbolAddress((void**)&dCur2, g_cur2);
    cudaFuncSetAttribute(chol_linv_fused, cudaFuncAttributeMaxDynamicSharedMemorySize,
                         FUSED_SMEM);
    cudaFuncSetAttribute(gemm_mma<0, 0>, cudaFuncAttributeMaxDynamicSharedMemorySize,
                         MMA_SMEM);
    cudaFuncSetAttribute(gemm_mma<1, 1>, cudaFuncAttributeMaxDynamicSharedMemorySize,
                         MMA_SMEM);

    // zero Linv (strict-upper must be zero for the bisection reads)
    cudaMemsetAsync(dLinv, 0, (size_t)Nn * Nn * sizeof(float));

    // ---- Layer A: M = I + Va^T Va ; factor+inv ; a_weight = Va Linv^T ----
    gm<1, 1>(Va, Nn, 0, Va, Nn, 0, Nn, dA, Nn, 0, Nn, Nn, nullptr, 1.0f, 0.0f, 1.0f, 2, 1);
    chol_linv_fused<<<CHB, 256, FUSED_SMEM>>>(dA, dLinv, dTmp);
    gm<0, 0>(Va, Nn, 0, dLinv, Nn, 0, Nn, dAw, Nn, 0, Nn, Nn, nullptr, 1.0f, 0.0f, 0.0f, 0, 1);

    // first = x @ a_weight^T + ba -> out
    gm<0, 0>(x, Nn, 0, dAw, Nn, 0, Nn, out, Nn, 0, BATCH, Nn, ba, 1.0f, 0.0f, 0.0f, 0, 1);
    cudaMemcpyAsync(dCur, x, (size_t)BATCH * Nn * sizeof(float), cudaMemcpyDeviceToDevice);

    float* cur = dCur;
    float* cur2 = dCur2;
    for (int i = 0; i < NL; ++i) {
        // T = gamma @ Linv^T  (layer 0: gamma = I -> T = Linv^T)
        if (i == 0)
            transpose_kernel<<<dim3(32, 32), dim3(32, 32)>>>(dLinv, dT);
        else
            gm<0, 0>(dGamma, Nn, 0, dLinv, Nn, 0, Nn, dT, Nn, 0, Nn, Nn, nullptr, 1.0f,
                     0.0f, 0.0f, 0, 1);
        // W = V_i @ Linv^T
        gm<0, 0>(Vin + (size_t)i * Nn * Nn, Nn, 0, dLinv, Nn, 0, Nn, dW, Nn, 0, Nn, Nn,
                 nullptr, 1.0f, 0.0f, 0.0f, 0, 1);
        // cur = relu(cur @ W^T + b_i)
        gm<0, 0>(cur, Nn, 0, dW, Nn, 0, Nn, cur2, Nn, 0, BATCH, Nn, bin + (size_t)i * Nn,
                 1.0f, 0.0f, 0.0f, 1, 1);
        { float* t = cur; cur = cur2; cur2 = t; }
        // S += T T^T
        gm<0, 0>(dT, Nn, 0, dT, Nn, 0, Nn, dS, Nn, 0, Nn, Nn, nullptr, 1.0f,
                 (i == 0) ? 0.0f : 1.0f, 0.0f, 0, 1);
        // gamma = T @ W^T
        gm<0, 0>(dT, Nn, 0, dW, Nn, 0, Nn, dGamma, Nn, 0, Nn, Nn, nullptr, 1.0f, 0.0f,
                 0.0f, 0, 1);
        // M = I + 0.5 W W^T ; factor+inv
        gm<0, 0>(dW, Nn, 0, dW, Nn, 0, Nn, dA, Nn, 0, Nn, Nn, nullptr, 0.5f, 0.0f, 1.0f, 2, 1);
        chol_linv_fused<<<CHB, 256, FUSED_SMEM>>>(dA, dLinv, dTmp);
    }

    // ---- Final layer B ----
    gm<0, 0>(Vb, Nn, 0, dLinv, Nn, 0, Nn, dGamma, Nn, 0, Nn, Nn, nullptr, 1.0f, 0.0f, 0.0f, 0, 1);
    gm<0, 0>(dAw, Nn, 0, dS, Nn, 0, Nn, dT, Nn, 0, Nn, Nn, nullptr, 1.0f, 0.0f, 0.0f, 0, 1);
    gm<0, 0>(dT, Nn, 0, dAw, Nn, 0, Nn, dA, Nn, 0, Nn, Nn, nullptr, 1.0f, 0.0f, 1.0f, 2, 1);
    chol_linv_fused<<<CHB, 256, FUSED_SMEM>>>(dA, dLinv, dTmp);
    gm<1, 1>(dLinv, Nn, 0, dGamma, Nn, 0, Nn, dW, Nn, 0, Nn, Nn, nullptr, 1.0f, 0.0f, 0.0f, 0, 1);
    gm<0, 0>(cur, Nn, 0, dW, Nn, 0, Nn, out, Nn, 0, BATCH, Nn, nullptr, 1.0f, 1.0f, 0.0f, 0, 1);
}